// round 7
// baseline (speedup 1.0000x reference)
#include <cuda_runtime.h>
#include <cuda_fp16.h>
#include <cstdint>

#define NTOK 65536
#define DM   256
#define NE   8
#define MT   64
#define TPE  (NTOK / MT)          // 1024
#define GT   256
#define KB   32                   // k per chunk
#define NBUF 4
#define NCHT 16                   // 8 chunks W1 + 8 chunks W2
#define XS_H 264                  // half stride of Xs rows (132 words = 4 mod 32)
#define WS_N 264                  // half2 stride of W k2-rows (264 = 8 mod 32)
#define CHUNK_H2 4096             // 16 k2 x 256 n half2 per chunk
#define CHUNK_B  16384

// ---------------- device scratch (no allocation allowed) -------------------
__device__ int     g_cnt[NE];
__device__ int     g_off[NE];
__device__ int     g_assign[NTOK];
__device__ int     g_ticket[NTOK];
__device__ float   g_gate[NTOK];
__device__ int     g_perm[NTOK];
// k-pair-packed half weights: [e][stage][k2=128][n=256] half2  (2 MB)
__device__ __half2 g_wh[NE * 2 * 128 * 256];

// ---------------- helpers ---------------------------------------------------
__device__ __forceinline__ uint32_t smem_u32(const void* p) {
    uint32_t a;
    asm("{ .reg .u64 t; cvta.to.shared.u64 t, %1; cvt.u32.u64 %0, t; }"
        : "=r"(a) : "l"(p));
    return a;
}
__device__ __forceinline__ void mma_f16(float c[4], const uint32_t a[4],
                                        uint32_t b0, uint32_t b1) {
    asm volatile(
        "mma.sync.aligned.m16n8k16.row.col.f32.f16.f16.f32 "
        "{%0,%1,%2,%3}, {%4,%5,%6,%7}, {%8,%9}, {%0,%1,%2,%3};\n"
        : "+f"(c[0]), "+f"(c[1]), "+f"(c[2]), "+f"(c[3])
        : "r"(a[0]), "r"(a[1]), "r"(a[2]), "r"(a[3]), "r"(b0), "r"(b1));
}
__device__ __forceinline__ void cp_async16(uint32_t dst, const void* src) {
    asm volatile("cp.async.cg.shared.global [%0], [%1], 16;"
                 :: "r"(dst), "l"(__cvta_generic_to_global(src)) : "memory");
}
__device__ __forceinline__ void cp_commit() {
    asm volatile("cp.async.commit_group;" ::: "memory");
}
__device__ __forceinline__ void cp_wait3() {
    asm volatile("cp.async.wait_group 3;" ::: "memory");
}

// ---------------- kernel 1: weight->half2 image (+ counter zero) ------------
__global__ void __launch_bounds__(256) whalf_kernel(
    const float* __restrict__ W1, const float* __restrict__ W2)
{
    if (blockIdx.x == 0 && threadIdx.x < NE) g_cnt[threadIdx.x] = 0;
    int idx = blockIdx.x * 256 + threadIdx.x;     // 524288 total
    int n  = idx & 255;
    int k2 = (idx >> 8) & 127;
    int st = (idx >> 15) & 1;
    int e  = idx >> 16;
    const float* src = (st ? W2 : W1) + (size_t)e * DM * DM;
    g_wh[idx] = __floats2half2_rn(src[(2 * k2) * DM + n],
                                  src[(2 * k2 + 1) * DM + n]);
}

// ---------------- kernel 2: routing (2 threads per token) -------------------
__global__ void __launch_bounds__(256) routing_kernel(
    const float* __restrict__ x, const float* __restrict__ wg)
{
    extern __shared__ float sm[];
    float* xS  = sm;                    // 128 rows x 264
    float* wgS = sm + 128 * 264;

    int tid = threadIdx.x;
    int tok0 = blockIdx.x * 128;

    for (int i = tid; i < NE * DM; i += 256) wgS[i] = wg[i];
    for (int i = tid; i < 128 * DM; i += 256) {
        int r = i >> 8, c = i & 255;
        xS[r * 264 + (c >> 7) * 132 + (c & 127)] = x[(size_t)(tok0 + r) * DM + c];
    }
    __syncthreads();

    int r = tid >> 1, h = tid & 1;
    const float4* xr  = (const float4*)(xS + r * 264 + h * 132);
    const float4* wg4 = (const float4*)wgS;

    float acc[NE];
    #pragma unroll
    for (int e = 0; e < NE; e++) acc[e] = 0.f;
    #pragma unroll 4
    for (int k4 = 0; k4 < 32; k4++) {
        float4 xv = xr[k4];
        #pragma unroll
        for (int e = 0; e < NE; e++) {
            float4 w = wg4[e * 64 + h * 32 + k4];
            acc[e] += xv.x * w.x + xv.y * w.y + xv.z * w.z + xv.w * w.w;
        }
    }
    #pragma unroll
    for (int e = 0; e < NE; e++)
        acc[e] += __shfl_xor_sync(0xffffffffu, acc[e], 1);

    int lane = tid & 31;
    if ((lane & 1) == 0) {
        float mx = acc[0]; int a = 0;
        #pragma unroll
        for (int e = 1; e < NE; e++) if (acc[e] > mx) { mx = acc[e]; a = e; }
        float s = 0.f;
        #pragma unroll
        for (int e = 0; e < NE; e++) s += __expf(acc[e] - mx);
        float gate = 1.0f / s;

        unsigned grp = __match_any_sync(0x55555555u, a);
        int leader = __ffs(grp) - 1;
        int rank   = __popc(grp & ((1u << lane) - 1));
        int base = 0;
        if (lane == leader) base = atomicAdd(&g_cnt[a], __popc(grp));
        base = __shfl_sync(0x55555555u, base, leader);

        int tok = tok0 + r;
        g_assign[tok] = a;
        g_ticket[tok] = base + rank;
        g_gate[tok]   = gate;
    }
}

// ---------------- kernel 3: perm (scan fused) --------------------------------
__global__ void __launch_bounds__(1024) perm_kernel() {
    __shared__ int offS[NE];
    if (threadIdx.x == 0) {
        int s = 0;
        #pragma unroll
        for (int e = 0; e < NE; e++) { offS[e] = s; s += g_cnt[e]; }
        if (blockIdx.x == 0) {
            #pragma unroll
            for (int e = 0; e < NE; e++) g_off[e] = offS[e];
        }
    }
    __syncthreads();
    int i = blockIdx.x * blockDim.x + threadIdx.x;
    g_perm[offS[g_assign[i]] + g_ticket[i]] = i;
}

// ---------------- GEMM pieces ------------------------------------------------
__device__ __forceinline__ void issue_chunk(uint32_t wsm, int buf,
                                            const __half2* src, int tid) {
    uint32_t dbase = wsm + buf * (16 * WS_N * 4);
    #pragma unroll
    for (int j = 0; j < 4; j++) {
        int q = tid + j * GT;             // 16B unit: 4 half2
        int r = q >> 6, c4 = q & 63;
        cp_async16(dbase + (r * WS_N + c4 * 4) * 4, src + q * 4);
    }
    cp_commit();
}

__device__ __forceinline__ void compute_chunk(
    const __half* __restrict__ Xs, const uint32_t* __restrict__ Wb,
    float acc[2][8][4], int kb, int wm, int wn, int g, int tg)
{
    #pragma unroll
    for (int s = 0; s < 2; s++) {
        int khalf = kb * KB + s * 16;
        uint32_t a[2][4];
        #pragma unroll
        for (int mi = 0; mi < 2; mi++) {
            const __half* xr = Xs + (wm * 32 + mi * 16 + g) * XS_H + khalf + 2 * tg;
            a[mi][0] = *(const uint32_t*)(xr);
            a[mi][1] = *(const uint32_t*)(xr + 8 * XS_H);
            a[mi][2] = *(const uint32_t*)(xr + 8);
            a[mi][3] = *(const uint32_t*)(xr + 8 * XS_H + 8);
        }
        const uint32_t* wrow0 = Wb + (s * 8 + tg) * WS_N;
        const uint32_t* wrow1 = Wb + (s * 8 + tg + 4) * WS_N;
        #pragma unroll
        for (int ni = 0; ni < 8; ni++) {
            int bc = wn * 64 + ni * 8 + g;
            uint32_t b0 = wrow0[bc];
            uint32_t b1 = wrow1[bc];
            mma_f16(acc[0][ni], a[0], b0, b1);
            mma_f16(acc[1][ni], a[1], b0, b1);
        }
    }
}

// ---------------- kernel 4: grouped FFN --------------------------------------
__global__ void __launch_bounds__(GT, 2) moe_gemm_kernel(
    const float* __restrict__ x,
    const float* __restrict__ b1, const float* __restrict__ b2,
    float* __restrict__ out)
{
    int e = blockIdx.x >> 10;               // / TPE
    int t = blockIdx.x & (TPE - 1);
    int cnt = g_cnt[e];
    int m0 = t * MT;
    if (m0 >= cnt) return;
    int rows = min(MT, cnt - m0);
    int base = g_off[e] + m0;

    extern __shared__ char sraw[];
    int*    tokS  = (int*)sraw;                        // 64
    float*  gateS = (float*)(sraw + 256);              // 64
    float*  biasS = (float*)(sraw + 512);              // 256
    __half* Xs    = (__half*)(sraw + 1536);            // 64*264 halves = 33792 B
    char*   Wring = sraw + 1536 + MT * XS_H * 2;       // 4 * 16*264*4 B
    uint32_t wsm  = smem_u32(Wring);

    int tid  = threadIdx.x;
    int lane = tid & 31, warp = tid >> 5;
    int wm = warp & 1, wn = warp >> 1;
    int g = lane >> 2, tg = lane & 3;

    const __half2* wsrc = g_wh + (size_t)e * 16 * CHUNK_H2;
    #pragma unroll
    for (int c = 0; c < NBUF; c++)
        issue_chunk(wsm, c, wsrc + c * CHUNK_H2, tid);

    if (tid < MT) {
        int tok = (tid < rows) ? g_perm[base + tid] : -1;
        tokS[tid]  = tok;
        gateS[tid] = (tok >= 0) ? g_gate[tok] : 0.f;
    }
    for (int i = tid; i < DM; i += GT) biasS[i] = b1[e * DM + i];
    __syncthreads();

    // gather X tile -> half, zero-pad invalid rows
    #pragma unroll
    for (int j = 0; j < MT * 64 / GT; j++) {
        int i = tid + j * GT;
        int r = i >> 6, c4 = i & 63;
        float4 v = make_float4(0.f, 0.f, 0.f, 0.f);
        int tok = tokS[r];
        if (tok >= 0)
            v = *reinterpret_cast<const float4*>(x + (size_t)tok * DM + c4 * 4);
        __half2* p = (__half2*)(Xs + r * XS_H + c4 * 4);
        p[0] = __floats2half2_rn(v.x, v.y);
        p[1] = __floats2half2_rn(v.z, v.w);
    }
    __syncthreads();

    float acc[2][8][4];
    #pragma unroll
    for (int mi = 0; mi < 2; mi++)
        #pragma unroll
        for (int ni = 0; ni < 8; ni++)
            #pragma unroll
            for (int q = 0; q < 4; q++) acc[mi][ni][q] = 0.f;

    for (int i = 0; i < NCHT; i++) {
        if (i == 8) {
            // epilogue 1: H = half(relu(D1 + b1)) -> Xs
            #pragma unroll
            for (int mi = 0; mi < 2; mi++) {
                #pragma unroll
                for (int ni = 0; ni < 8; ni++) {
                    int col = wn * 64 + ni * 8 + tg * 2;
                    int r0  = wm * 32 + mi * 16 + g;
                    float bq0 = biasS[col], bq1 = biasS[col + 1];
                    float v00 = fmaxf(acc[mi][ni][0] + bq0, 0.f);
                    float v01 = fmaxf(acc[mi][ni][1] + bq1, 0.f);
                    float v10 = fmaxf(acc[mi][ni][2] + bq0, 0.f);
                    float v11 = fmaxf(acc[mi][ni][3] + bq1, 0.f);
                    *(__half2*)(Xs + r0 * XS_H + col)       = __floats2half2_rn(v00, v01);
                    *(__half2*)(Xs + (r0 + 8) * XS_H + col) = __floats2half2_rn(v10, v11);
                }
            }
            #pragma unroll
            for (int mi = 0; mi < 2; mi++)
                #pragma unroll
                for (int ni = 0; ni < 8; ni++)
                    #pragma unroll
                    for (int q = 0; q < 4; q++) acc[mi][ni][q] = 0.f;
        }
        cp_wait3();
        __syncthreads();                 // also orders epilogue-1 Xs writes
        if (i == 8) {
            for (int j = tid; j < DM; j += GT) biasS[j] = b2[e * DM + j];
        }
        compute_chunk(Xs, (const uint32_t*)(Wring + (i & 3) * (16 * WS_N * 4)),
                      acc, i & 7, wm, wn, g, tg);
        __syncthreads();
        if (i + NBUF < NCHT)
            issue_chunk(wsm, i & 3, wsrc + (i + NBUF) * CHUNK_H2, tid);
        else
            cp_commit();                 // keep group count uniform for wait3
    }

    // epilogue 2: out[tok] = (D2 + b2) * gate
    #pragma unroll
    for (int mi = 0; mi < 2; mi++) {
        #pragma unroll
        for (int rr = 0; rr < 2; rr++) {
            int r = wm * 32 + mi * 16 + rr * 8 + g;
            int tok = tokS[r];
            if (tok >= 0) {
                float gt = gateS[r];
                float* orow = out + (size_t)tok * DM;
                #pragma unroll
                for (int ni = 0; ni < 8; ni++) {
                    int col = wn * 64 + ni * 8 + tg * 2;
                    float2 v;
                    v.x = (acc[mi][ni][rr * 2 + 0] + biasS[col])     * gt;
                    v.y = (acc[mi][ni][rr * 2 + 1] + biasS[col + 1]) * gt;
                    *reinterpret_cast<float2*>(orow + col) = v;
                }
            }
        }
    }
}

// ---------------- launch -----------------------------------------------------
extern "C" void kernel_launch(void* const* d_in, const int* in_sizes, int n_in,
                              void* d_out, int out_size)
{
    const float* x  = (const float*)d_in[0];
    const float* wg = (const float*)d_in[1];
    const float* W1 = (const float*)d_in[2];
    const float* b1 = (const float*)d_in[3];
    const float* W2 = (const float*)d_in[4];
    const float* b2 = (const float*)d_in[5];
    float* out = (float*)d_out;

    const int rt_smem = (128 * 264 + NE * DM) * 4;
    const int gm_smem = 1536 + MT * XS_H * 2 + NBUF * 16 * WS_N * 4;
    cudaFuncSetAttribute(routing_kernel,
                         cudaFuncAttributeMaxDynamicSharedMemorySize, rt_smem);
    cudaFuncSetAttribute(moe_gemm_kernel,
                         cudaFuncAttributeMaxDynamicSharedMemorySize, gm_smem);

    whalf_kernel<<<2048, 256>>>(W1, W2);            // launch 1 (also zeros cnt)
    routing_kernel<<<NTOK / 128, 256, rt_smem>>>(x, wg);   // launch 2
    perm_kernel<<<64, 1024>>>();                    // launch 3 (scan fused)
    moe_gemm_kernel<<<NE * TPE, GT, gm_smem>>>(x, b1, b2, out);  // launch 4
}

// round 13
// speedup vs baseline: 1.2905x; 1.2905x over previous
#include <cuda_runtime.h>
#include <cuda_fp16.h>
#include <cstdint>

#define NTOK 65536
#define DM   256
#define NE   8
#define MT   64
#define CPE  18                   // CTAs per expert (8*18=144 = one wave)
#define FT   512                  // ffn threads
#define WS_N 264                  // uint32 stride of W k2-rows
#define XS_H 264                  // half stride of Xs rows

// ---------------- device scratch (no allocation allowed) -------------------
__device__ int     g_cnt[NE] = {0};
__device__ int     g_off[NE];
__device__ int     g_assign[NTOK];
__device__ int     g_ticket[NTOK];
__device__ float   g_gate[NTOK];
__device__ int     g_perm[NTOK];
// hidden activations in slot order; +MT rows of padding for ragged tail reads
__device__ __half2 g_h[(NTOK + MT) * (DM / 2)];

// ---------------- helpers ---------------------------------------------------
__device__ __forceinline__ uint32_t h2u(__half2 h) {
    union { __half2 h; uint32_t u; } c;
    c.h = h;
    return c.u;
}
__device__ __forceinline__ uint32_t pack2(float a, float b) {
    return h2u(__floats2half2_rn(a, b));
}
__device__ __forceinline__ uint32_t smem_u32(const void* p) {
    uint32_t a;
    asm("{ .reg .u64 t; cvta.to.shared.u64 t, %1; cvt.u32.u64 %0, t; }"
        : "=r"(a) : "l"(p));
    return a;
}
__device__ __forceinline__ void mma_f16(float c[4], const uint32_t a[4],
                                        uint32_t b0, uint32_t b1) {
    asm volatile(
        "mma.sync.aligned.m16n8k16.row.col.f32.f16.f16.f32 "
        "{%0,%1,%2,%3}, {%4,%5,%6,%7}, {%8,%9}, {%0,%1,%2,%3};\n"
        : "+f"(c[0]), "+f"(c[1]), "+f"(c[2]), "+f"(c[3])
        : "r"(a[0]), "r"(a[1]), "r"(a[2]), "r"(a[3]), "r"(b0), "r"(b1));
}
__device__ __forceinline__ void ldm_x4(uint32_t r[4], uint32_t addr) {
    asm volatile("ldmatrix.sync.aligned.m8n8.x4.shared.b16 {%0,%1,%2,%3}, [%4];"
                 : "=r"(r[0]), "=r"(r[1]), "=r"(r[2]), "=r"(r[3]) : "r"(addr));
}

// ---------------- kernel 1: routing (2 threads per token) -------------------
__global__ void __launch_bounds__(256) routing_kernel(
    const float* __restrict__ x, const float* __restrict__ wg)
{
    extern __shared__ float sm[];
    float* xS  = sm;                    // 128 rows x 264
    float* wgS = sm + 128 * 264;

    int tid = threadIdx.x;
    int tok0 = blockIdx.x * 128;

    for (int i = tid; i < NE * DM; i += 256) wgS[i] = wg[i];
    for (int i = tid; i < 128 * DM; i += 256) {
        int r = i >> 8, c = i & 255;
        xS[r * 264 + (c >> 7) * 132 + (c & 127)] = x[(size_t)(tok0 + r) * DM + c];
    }
    __syncthreads();

    int r = tid >> 1, h = tid & 1;
    const float4* xr  = (const float4*)(xS + r * 264 + h * 132);
    const float4* wg4 = (const float4*)wgS;

    float acc[NE];
    #pragma unroll
    for (int e = 0; e < NE; e++) acc[e] = 0.f;
    #pragma unroll 4
    for (int k4 = 0; k4 < 32; k4++) {
        float4 xv = xr[k4];
        #pragma unroll
        for (int e = 0; e < NE; e++) {
            float4 w = wg4[e * 64 + h * 32 + k4];
            acc[e] += xv.x * w.x + xv.y * w.y + xv.z * w.z + xv.w * w.w;
        }
    }
    #pragma unroll
    for (int e = 0; e < NE; e++)
        acc[e] += __shfl_xor_sync(0xffffffffu, acc[e], 1);

    int lane = tid & 31;
    if ((lane & 1) == 0) {
        float mx = acc[0]; int a = 0;
        #pragma unroll
        for (int e = 1; e < NE; e++) if (acc[e] > mx) { mx = acc[e]; a = e; }
        float s = 0.f;
        #pragma unroll
        for (int e = 0; e < NE; e++) s += __expf(acc[e] - mx);
        float gate = 1.0f / s;

        unsigned grp = __match_any_sync(0x55555555u, a);
        int leader = __ffs(grp) - 1;
        int rank   = __popc(grp & ((1u << lane) - 1));
        int base = 0;
        if (lane == leader) base = atomicAdd(&g_cnt[a], __popc(grp));
        base = __shfl_sync(0x55555555u, base, leader);

        int tok = tok0 + r;
        g_assign[tok] = a;
        g_ticket[tok] = base + rank;
        g_gate[tok]   = gate;
    }
}

// ---------------- kernel 2: perm (scan fused) --------------------------------
__global__ void __launch_bounds__(1024) perm_kernel() {
    __shared__ int offS[NE];
    if (threadIdx.x == 0) {
        int s = 0;
        #pragma unroll
        for (int e = 0; e < NE; e++) { offS[e] = s; s += g_cnt[e]; }
        if (blockIdx.x == 0) {
            #pragma unroll
            for (int e = 0; e < NE; e++) g_off[e] = offS[e];
        }
    }
    __syncthreads();
    int i = blockIdx.x * blockDim.x + threadIdx.x;
    g_perm[offS[g_assign[i]] + g_ticket[i]] = i;
}

// ---------------- shared FFN pieces -----------------------------------------
// W smem image: uint32 Ws[k2=128][WS_N], Ws[k2][n] = half2(W[2k2][n], W[2k2+1][n])
__device__ __forceinline__ void load_weights(uint32_t* __restrict__ Ws,
                                             const float* __restrict__ Wg, int tid) {
    #pragma unroll
    for (int j = 0; j < 16; j++) {
        int idx = tid + j * FT;               // 8192 (k2, n4) pairs
        int k2 = idx >> 6, n4 = idx & 63;
        float4 lo = *(const float4*)(Wg + (2 * k2) * DM + n4 * 4);
        float4 hi = *(const float4*)(Wg + (2 * k2 + 1) * DM + n4 * 4);
        uint4 v;
        v.x = pack2(lo.x, hi.x);
        v.y = pack2(lo.y, hi.y);
        v.z = pack2(lo.z, hi.z);
        v.w = pack2(lo.w, hi.w);
        *(uint4*)(Ws + k2 * WS_N + n4 * 4) = v;
    }
}

// k-loop: D(64x256) += Xs(64x256 half) @ Ws ; warp tile m32 x n32
__device__ __forceinline__ void kloop(const uint32_t* __restrict__ Ws,
                                      uint32_t aAddr0, uint32_t aAddr1,
                                      int bc, int tg, float acc[2][4][4])
{
    #pragma unroll
    for (int mi = 0; mi < 2; mi++)
        #pragma unroll
        for (int ni = 0; ni < 4; ni++)
            #pragma unroll
            for (int q = 0; q < 4; q++) acc[mi][ni][q] = 0.f;

    #pragma unroll 4
    for (int ks = 0; ks < 16; ks++) {
        uint32_t a0[4], a1[4];
        ldm_x4(a0, aAddr0 + ks * 32);
        ldm_x4(a1, aAddr1 + ks * 32);
        const uint32_t* w0 = Ws + (ks * 8 + tg) * WS_N + bc;
        const uint32_t* w1 = w0 + 4 * WS_N;
        #pragma unroll
        for (int ni = 0; ni < 4; ni++) {
            uint32_t b0 = w0[ni * 8];
            uint32_t b1 = w1[ni * 8];
            mma_f16(acc[0][ni], a0, b0, b1);
            mma_f16(acc[1][ni], a1, b0, b1);
        }
    }
}

// ---------------- kernel 3: stage-1 FFN (gather -> relu -> H) ----------------
__global__ void __launch_bounds__(FT, 1) ffn1_kernel(
    const float* __restrict__ x, const float* __restrict__ W1,
    const float* __restrict__ b1)
{
    int e   = blockIdx.x / CPE;
    int sub = blockIdx.x % CPE;
    int cnt = g_cnt[e];
    int ntiles = (cnt + MT - 1) >> 6;
    int base_e = g_off[e];

    extern __shared__ char sraw[];
    uint32_t* Ws  = (uint32_t*)sraw;                       // 135168 B
    __half*  Xs   = (__half*)(sraw + 128 * WS_N * 4);      // 33792 B
    float* biasS  = (float*)(sraw + 128 * WS_N * 4 + MT * XS_H * 2);  // 1024 B

    int tid = threadIdx.x;
    int lane = tid & 31, warp = tid >> 5;
    int wm = warp & 1, wn = warp >> 1;
    int g = lane >> 2, tg = lane & 3;
    int bc = wn * 32 + g;

    load_weights(Ws, W1 + (size_t)e * DM * DM, tid);
    for (int i = tid; i < DM; i += FT) biasS[i] = b1[e * DM + i];

    uint32_t xsb = smem_u32(Xs);
    int rowA = wm * 32 + (lane & 7) + ((lane >> 3) & 1) * 8;
    int khA  = ((lane >> 4) & 1) * 8;
    uint32_t aAddr0 = xsb + (rowA * XS_H + khA) * 2;
    uint32_t aAddr1 = aAddr0 + 16 * XS_H * 2;

    for (int t = sub; t < ntiles; t += CPE) {
        int m0 = t * MT;
        int rows = min(MT, cnt - m0);
        int base = base_e + m0;

        __syncthreads();   // previous iteration's k-loop readers done; also W/bias ready
        // gather X -> half
        #pragma unroll
        for (int j = 0; j < MT * 64 / FT; j++) {
            int i = tid + j * FT;
            int r = i >> 6, c4 = i & 63;
            float4 v = make_float4(0.f, 0.f, 0.f, 0.f);
            if (r < rows) {
                int tok = g_perm[base + r];
                v = *(const float4*)(x + (size_t)tok * DM + c4 * 4);
            }
            uint2 p;
            p.x = pack2(v.x, v.y);
            p.y = pack2(v.z, v.w);
            *(uint2*)(Xs + r * XS_H + c4 * 4) = p;
        }
        __syncthreads();

        float acc[2][4][4];
        kloop(Ws, aAddr0, aAddr1, bc, tg, acc);

        // epilogue: H = half(relu(D + b1)) -> g_h in slot order.
        // MUST guard r < rows: spill rows would land in the next expert's
        // slot range (race/corruption) and past g_h for the last expert.
        #pragma unroll
        for (int mi = 0; mi < 2; mi++) {
            #pragma unroll
            for (int rr = 0; rr < 2; rr++) {
                int r = wm * 32 + mi * 16 + rr * 8 + g;
                if (r < rows) {
                    __half2* hrow = g_h + (size_t)(base + r) * (DM / 2);
                    #pragma unroll
                    for (int ni = 0; ni < 4; ni++) {
                        int col = wn * 32 + ni * 8 + tg * 2;
                        float v0 = fmaxf(acc[mi][ni][rr * 2 + 0] + biasS[col], 0.f);
                        float v1 = fmaxf(acc[mi][ni][rr * 2 + 1] + biasS[col + 1], 0.f);
                        hrow[col >> 1] = __floats2half2_rn(v0, v1);
                    }
                }
            }
        }
    }
}

// ---------------- kernel 4: stage-2 FFN (H -> scatter out) -------------------
__global__ void __launch_bounds__(FT, 1) ffn2_kernel(
    const float* __restrict__ W2, const float* __restrict__ b2,
    float* __restrict__ out)
{
    int e   = blockIdx.x / CPE;
    int sub = blockIdx.x % CPE;
    int cnt = g_cnt[e];
    int ntiles = (cnt + MT - 1) >> 6;
    int base_e = g_off[e];

    extern __shared__ char sraw[];
    uint32_t* Ws  = (uint32_t*)sraw;
    __half*  Xs   = (__half*)(sraw + 128 * WS_N * 4);
    float* biasS  = (float*)(sraw + 128 * WS_N * 4 + MT * XS_H * 2);
    int*   tokS   = (int*)(biasS + DM);                    // 64 ints
    float* gateS  = (float*)(tokS + MT);                   // 64 floats

    int tid = threadIdx.x;
    int lane = tid & 31, warp = tid >> 5;
    int wm = warp & 1, wn = warp >> 1;
    int g = lane >> 2, tg = lane & 3;
    int bc = wn * 32 + g;

    load_weights(Ws, W2 + (size_t)e * DM * DM, tid);
    for (int i = tid; i < DM; i += FT) biasS[i] = b2[e * DM + i];

    uint32_t xsb = smem_u32(Xs);
    int rowA = wm * 32 + (lane & 7) + ((lane >> 3) & 1) * 8;
    int khA  = ((lane >> 4) & 1) * 8;
    uint32_t aAddr0 = xsb + (rowA * XS_H + khA) * 2;
    uint32_t aAddr1 = aAddr0 + 16 * XS_H * 2;

    for (int t = sub; t < ntiles; t += CPE) {
        int m0 = t * MT;
        int rows = min(MT, cnt - m0);
        int base = base_e + m0;

        __syncthreads();
        // load H tile (contiguous slot order; tail rows read pad/foreign slots,
        // in-bounds thanks to g_h padding, and are discarded via tok guard)
        #pragma unroll
        for (int j = 0; j < MT * 32 / FT; j++) {
            int i = tid + j * FT;
            int r = i >> 5, c = i & 31;       // 32 x uint4 per row
            uint4 v = *((const uint4*)(g_h + (size_t)(base + r) * (DM / 2)) + c);
            *(uint4*)(Xs + r * XS_H + c * 8) = v;
        }
        if (tid < MT) {
            int tok = (tid < rows) ? g_perm[base + tid] : -1;
            tokS[tid]  = tok;
            gateS[tid] = (tok >= 0) ? g_gate[tok] : 0.f;
        }
        __syncthreads();

        float acc[2][4][4];
        kloop(Ws, aAddr0, aAddr1, bc, tg, acc);

        // epilogue: out[tok] = (D + b2) * gate
        #pragma unroll
        for (int mi = 0; mi < 2; mi++) {
            #pragma unroll
            for (int rr = 0; rr < 2; rr++) {
                int r = wm * 32 + mi * 16 + rr * 8 + g;
                int tok = tokS[r];
                if (tok >= 0) {
                    float gt = gateS[r];
                    float* orow = out + (size_t)tok * DM;
                    #pragma unroll
                    for (int ni = 0; ni < 4; ni++) {
                        int col = wn * 32 + ni * 8 + tg * 2;
                        float2 v;
                        v.x = (acc[mi][ni][rr * 2 + 0] + biasS[col])     * gt;
                        v.y = (acc[mi][ni][rr * 2 + 1] + biasS[col + 1]) * gt;
                        *(float2*)(orow + col) = v;
                    }
                }
            }
        }
    }
}

// ---------------- kernel 5: re-zero counters for next graph replay ----------
__global__ void ztail_kernel() {
    if (threadIdx.x < NE) g_cnt[threadIdx.x] = 0;
}

// ---------------- launch -----------------------------------------------------
extern "C" void kernel_launch(void* const* d_in, const int* in_sizes, int n_in,
                              void* d_out, int out_size)
{
    const float* x  = (const float*)d_in[0];
    const float* wg = (const float*)d_in[1];
    const float* W1 = (const float*)d_in[2];
    const float* b1 = (const float*)d_in[3];
    const float* W2 = (const float*)d_in[4];
    const float* b2 = (const float*)d_in[5];
    float* out = (float*)d_out;

    const int rt_smem = (128 * 264 + NE * DM) * 4;
    const int ff_smem = 128 * WS_N * 4 + MT * XS_H * 2 + DM * 4 + MT * 4 + MT * 4;
    cudaFuncSetAttribute(routing_kernel,
                         cudaFuncAttributeMaxDynamicSharedMemorySize, rt_smem);
    cudaFuncSetAttribute(ffn1_kernel,
                         cudaFuncAttributeMaxDynamicSharedMemorySize, ff_smem);
    cudaFuncSetAttribute(ffn2_kernel,
                         cudaFuncAttributeMaxDynamicSharedMemorySize, ff_smem);

    routing_kernel<<<NTOK / 128, 256, rt_smem>>>(x, wg);      // 1
    perm_kernel<<<64, 1024>>>();                              // 2
    ffn1_kernel<<<NE * CPE, FT, ff_smem>>>(x, W1, b1);        // 3
    ffn2_kernel<<<NE * CPE, FT, ff_smem>>>(W2, b2, out);      // 4 (profiled)
    ztail_kernel<<<1, 32>>>();                                // 5
}

// round 14
// speedup vs baseline: 1.3463x; 1.0433x over previous
#include <cuda_runtime.h>
#include <cuda_fp16.h>
#include <cstdint>

#define NTOK 65536
#define DM   256
#define NE   8
#define MT   128
#define CPE  18                   // CTAs per expert (8*18=144 = one wave)
#define FT   512
#define WS_S 516                  // word stride of packed B rows (516/4 odd -> cf)
#define XS_H 264                  // half stride of Xs rows

// ---------------- device scratch (no allocation allowed) -------------------
__device__ int     g_cnt[NE] = {0};
__device__ int     g_off[NE];
__device__ int     g_assign[NTOK];
__device__ int     g_ticket[NTOK];
__device__ float   g_gate[NTOK];
__device__ int     g_perm[NTOK];
// hidden activations in slot order; +MT rows padding for ragged tail reads
__device__ __half2 g_h[(NTOK + MT) * (DM / 2)];

// ---------------- helpers ---------------------------------------------------
__device__ __forceinline__ uint32_t h2u(__half2 h) {
    union { __half2 h; uint32_t u; } c;
    c.h = h;
    return c.u;
}
__device__ __forceinline__ uint32_t pack2(float a, float b) {
    return h2u(__floats2half2_rn(a, b));
}
__device__ __forceinline__ uint32_t smem_u32(const void* p) {
    uint32_t a;
    asm("{ .reg .u64 t; cvta.to.shared.u64 t, %1; cvt.u32.u64 %0, t; }"
        : "=r"(a) : "l"(p));
    return a;
}
__device__ __forceinline__ void mma_f16(float c[4], const uint32_t a[4],
                                        uint32_t b0, uint32_t b1) {
    asm volatile(
        "mma.sync.aligned.m16n8k16.row.col.f32.f16.f16.f32 "
        "{%0,%1,%2,%3}, {%4,%5,%6,%7}, {%8,%9}, {%0,%1,%2,%3};\n"
        : "+f"(c[0]), "+f"(c[1]), "+f"(c[2]), "+f"(c[3])
        : "r"(a[0]), "r"(a[1]), "r"(a[2]), "r"(a[3]), "r"(b0), "r"(b1));
}
__device__ __forceinline__ void ldm_x4(uint32_t r[4], uint32_t addr) {
    asm volatile("ldmatrix.sync.aligned.m8n8.x4.shared.b16 {%0,%1,%2,%3}, [%4];"
                 : "=r"(r[0]), "=r"(r[1]), "=r"(r[2]), "=r"(r[3]) : "r"(addr));
}

// ---------------- kernel 1: routing (2 threads per token) -------------------
__global__ void __launch_bounds__(256) routing_kernel(
    const float* __restrict__ x, const float* __restrict__ wg)
{
    extern __shared__ float sm[];
    float* xS  = sm;                    // 128 rows x 264
    float* wgS = sm + 128 * 264;

    int tid = threadIdx.x;
    int tok0 = blockIdx.x * 128;

    for (int i = tid; i < NE * DM; i += 256) wgS[i] = wg[i];
    for (int i = tid; i < 128 * DM; i += 256) {
        int r = i >> 8, c = i & 255;
        xS[r * 264 + (c >> 7) * 132 + (c & 127)] = x[(size_t)(tok0 + r) * DM + c];
    }
    __syncthreads();

    int r = tid >> 1, h = tid & 1;
    const float4* xr  = (const float4*)(xS + r * 264 + h * 132);
    const float4* wg4 = (const float4*)wgS;

    float acc[NE];
    #pragma unroll
    for (int e = 0; e < NE; e++) acc[e] = 0.f;
    #pragma unroll 4
    for (int k4 = 0; k4 < 32; k4++) {
        float4 xv = xr[k4];
        #pragma unroll
        for (int e = 0; e < NE; e++) {
            float4 w = wg4[e * 64 + h * 32 + k4];
            acc[e] += xv.x * w.x + xv.y * w.y + xv.z * w.z + xv.w * w.w;
        }
    }
    #pragma unroll
    for (int e = 0; e < NE; e++)
        acc[e] += __shfl_xor_sync(0xffffffffu, acc[e], 1);

    int lane = tid & 31;
    if ((lane & 1) == 0) {
        float mx = acc[0]; int a = 0;
        #pragma unroll
        for (int e = 1; e < NE; e++) if (acc[e] > mx) { mx = acc[e]; a = e; }
        float s = 0.f;
        #pragma unroll
        for (int e = 0; e < NE; e++) s += __expf(acc[e] - mx);
        float gate = 1.0f / s;

        unsigned grp = __match_any_sync(0x55555555u, a);
        int leader = __ffs(grp) - 1;
        int rank   = __popc(grp & ((1u << lane) - 1));
        int base = 0;
        if (lane == leader) base = atomicAdd(&g_cnt[a], __popc(grp));
        base = __shfl_sync(0x55555555u, base, leader);

        int tok = tok0 + r;
        g_assign[tok] = a;
        g_ticket[tok] = base + rank;
        g_gate[tok]   = gate;
    }
}

// ---------------- kernel 2: perm (scan fused) --------------------------------
__global__ void __launch_bounds__(1024) perm_kernel() {
    __shared__ int offS[NE];
    if (threadIdx.x == 0) {
        int s = 0;
        #pragma unroll
        for (int e = 0; e < NE; e++) { offS[e] = s; s += g_cnt[e]; }
        if (blockIdx.x == 0) {
            #pragma unroll
            for (int e = 0; e < NE; e++) g_off[e] = offS[e];
        }
    }
    __syncthreads();
    int i = blockIdx.x * blockDim.x + threadIdx.x;
    g_perm[offS[g_assign[i]] + g_ticket[i]] = i;
}

// ---------------- shared FFN pieces -----------------------------------------
// Packed B image: Ws[kq][c'] is a uint2 at word (kq*WS_S + c'*2):
//   kq = ks*4 + tg  (ks 0..15, tg 0..3), c' = wn*64 + g*8 + ni (n permuted)
//   .x = half2(W[2r][n],   W[2r+1][n])   (b0), r = ks*8 + tg
//   .y = half2(W[2r+8][n], W[2r+9][n])   (b1)
// n = wn*64 + ni*8 + g. One uint4 load = (b0,b1) for ni and ni+1.
__device__ __forceinline__ void load_weights(uint32_t* __restrict__ Ws,
                                             const float* __restrict__ Wg, int tid) {
    #pragma unroll
    for (int j = 0; j < 16; j++) {
        int idx = tid + j * FT;               // 8192 = 128 k2-rows x 64 n4
        int k2 = idx >> 6, n4 = idx & 63;
        float4 lo = *(const float4*)(Wg + (2 * k2) * DM + n4 * 4);
        float4 hi = *(const float4*)(Wg + (2 * k2 + 1) * DM + n4 * 4);
        int kq   = (k2 >> 3) * 4 + (k2 & 3);
        int slot = (k2 >> 2) & 1;             // 0 -> b0, 1 -> b1
        float L[4] = {lo.x, lo.y, lo.z, lo.w};
        float H[4] = {hi.x, hi.y, hi.z, hi.w};
        #pragma unroll
        for (int q = 0; q < 4; q++) {
            int n  = n4 * 4 + q;
            int cp = (n >> 6) * 64 + (n & 7) * 8 + ((n >> 3) & 7);
            Ws[kq * WS_S + cp * 2 + slot] = pack2(L[q], H[q]);
        }
    }
}

// k-loop: D(128x256) += Xs(128x256 half) @ W ; warp tile m32 x n64
__device__ __forceinline__ void kloop(const uint32_t* __restrict__ Ws,
                                      uint32_t aAddr0, uint32_t aAddr1,
                                      int wn, int g, int tg, float acc[2][8][4])
{
    #pragma unroll
    for (int mi = 0; mi < 2; mi++)
        #pragma unroll
        for (int ni = 0; ni < 8; ni++)
            #pragma unroll
            for (int q = 0; q < 4; q++) acc[mi][ni][q] = 0.f;

    const uint32_t* wbase = Ws + (size_t)tg * WS_S + (wn * 64 + g * 8) * 2;
    #pragma unroll 4
    for (int ks = 0; ks < 16; ks++) {
        uint32_t a0[4], a1[4];
        ldm_x4(a0, aAddr0 + ks * 32);
        ldm_x4(a1, aAddr1 + ks * 32);
        const uint4* wrow = (const uint4*)(wbase + ks * 4 * WS_S);
        #pragma unroll
        for (int nj = 0; nj < 4; nj++) {
            uint4 b = wrow[nj];
            mma_f16(acc[0][2 * nj],     a0, b.x, b.y);
            mma_f16(acc[1][2 * nj],     a1, b.x, b.y);
            mma_f16(acc[0][2 * nj + 1], a0, b.z, b.w);
            mma_f16(acc[1][2 * nj + 1], a1, b.z, b.w);
        }
    }
}

// ---------------- kernel 3: stage-1 FFN (gather -> relu -> H) ----------------
__global__ void __launch_bounds__(FT, 1) ffn1_kernel(
    const float* __restrict__ x, const float* __restrict__ W1,
    const float* __restrict__ b1)
{
    int e   = blockIdx.x / CPE;
    int sub = blockIdx.x % CPE;
    int cnt = g_cnt[e];
    int ntiles = (cnt + MT - 1) >> 7;
    int base_e = g_off[e];

    extern __shared__ char sraw[];
    uint32_t* Ws  = (uint32_t*)sraw;                       // 64*516*4 = 132096
    __half*  Xs   = (__half*)(sraw + 64 * WS_S * 4);       // 128*264*2 = 67584
    float* biasS  = (float*)(sraw + 64 * WS_S * 4 + MT * XS_H * 2);

    int tid = threadIdx.x;
    int lane = tid & 31, warp = tid >> 5;
    int wm = warp & 3, wn = warp >> 2;     // 4x4 warp grid: m32 x n64 tiles
    int g = lane >> 2, tg = lane & 3;

    load_weights(Ws, W1 + (size_t)e * DM * DM, tid);
    for (int i = tid; i < DM; i += FT) biasS[i] = b1[e * DM + i];

    uint32_t xsb = smem_u32(Xs);
    int rowA = wm * 32 + (lane & 7) + ((lane >> 3) & 1) * 8;
    int khA  = ((lane >> 4) & 1) * 8;
    uint32_t aAddr0 = xsb + (rowA * XS_H + khA) * 2;
    uint32_t aAddr1 = aAddr0 + 16 * XS_H * 2;

    for (int t = sub; t < ntiles; t += CPE) {
        int m0 = t * MT;
        int rows = min(MT, cnt - m0);
        int base = base_e + m0;

        __syncthreads();   // prev k-loop readers done; also W/bias ready
        // gather X -> half
        #pragma unroll
        for (int j = 0; j < MT * 64 / FT; j++) {
            int i = tid + j * FT;
            int r = i >> 6, c4 = i & 63;
            float4 v = make_float4(0.f, 0.f, 0.f, 0.f);
            if (r < rows) {
                int tok = g_perm[base + r];
                v = *(const float4*)(x + (size_t)tok * DM + c4 * 4);
            }
            uint2 p;
            p.x = pack2(v.x, v.y);
            p.y = pack2(v.z, v.w);
            *(uint2*)(Xs + r * XS_H + c4 * 4) = p;
        }
        __syncthreads();

        float acc[2][8][4];
        kloop(Ws, aAddr0, aAddr1, wn, g, tg, acc);

        // epilogue: H = half(relu(D + b1)) -> g_h slot order; guard r < rows
        #pragma unroll
        for (int mi = 0; mi < 2; mi++) {
            #pragma unroll
            for (int rr = 0; rr < 2; rr++) {
                int r = wm * 32 + mi * 16 + rr * 8 + g;
                if (r < rows) {
                    __half2* hrow = g_h + (size_t)(base + r) * (DM / 2);
                    #pragma unroll
                    for (int ni = 0; ni < 8; ni++) {
                        int col = wn * 64 + ni * 8 + tg * 2;
                        float v0 = fmaxf(acc[mi][ni][rr * 2 + 0] + biasS[col], 0.f);
                        float v1 = fmaxf(acc[mi][ni][rr * 2 + 1] + biasS[col + 1], 0.f);
                        hrow[col >> 1] = __floats2half2_rn(v0, v1);
                    }
                }
            }
        }
    }
}

// ---------------- kernel 4: stage-2 FFN (H -> scatter out) -------------------
__global__ void __launch_bounds__(FT, 1) ffn2_kernel(
    const float* __restrict__ W2, const float* __restrict__ b2,
    float* __restrict__ out)
{
    int e   = blockIdx.x / CPE;
    int sub = blockIdx.x % CPE;
    int cnt = g_cnt[e];
    int ntiles = (cnt + MT - 1) >> 7;
    int base_e = g_off[e];

    extern __shared__ char sraw[];
    uint32_t* Ws  = (uint32_t*)sraw;
    __half*  Xs   = (__half*)(sraw + 64 * WS_S * 4);
    float* biasS  = (float*)(sraw + 64 * WS_S * 4 + MT * XS_H * 2);
    int*   tokS   = (int*)(biasS + DM);                    // 128 ints
    float* gateS  = (float*)(tokS + MT);                   // 128 floats

    int tid = threadIdx.x;
    int lane = tid & 31, warp = tid >> 5;
    int wm = warp & 3, wn = warp >> 2;
    int g = lane >> 2, tg = lane & 3;

    load_weights(Ws, W2 + (size_t)e * DM * DM, tid);
    for (int i = tid; i < DM; i += FT) biasS[i] = b2[e * DM + i];

    uint32_t xsb = smem_u32(Xs);
    int rowA = wm * 32 + (lane & 7) + ((lane >> 3) & 1) * 8;
    int khA  = ((lane >> 4) & 1) * 8;
    uint32_t aAddr0 = xsb + (rowA * XS_H + khA) * 2;
    uint32_t aAddr1 = aAddr0 + 16 * XS_H * 2;

    for (int t = sub; t < ntiles; t += CPE) {
        int m0 = t * MT;
        int rows = min(MT, cnt - m0);
        int base = base_e + m0;

        __syncthreads();
        // load H tile (contiguous; tail rows read pad slots, discarded via tok)
        #pragma unroll
        for (int j = 0; j < MT * 32 / FT; j++) {
            int i = tid + j * FT;
            int r = i >> 5, c = i & 31;       // 32 x uint4 per row
            uint4 v = *((const uint4*)(g_h + (size_t)(base + r) * (DM / 2)) + c);
            *(uint4*)(Xs + r * XS_H + c * 8) = v;
        }
        if (tid < MT) {
            int tok = (tid < rows) ? g_perm[base + tid] : -1;
            tokS[tid]  = tok;
            gateS[tid] = (tok >= 0) ? g_gate[tok] : 0.f;
        }
        __syncthreads();

        float acc[2][8][4];
        kloop(Ws, aAddr0, aAddr1, wn, g, tg, acc);

        // epilogue: out[tok] = (D + b2) * gate
        #pragma unroll
        for (int mi = 0; mi < 2; mi++) {
            #pragma unroll
            for (int rr = 0; rr < 2; rr++) {
                int r = wm * 32 + mi * 16 + rr * 8 + g;
                int tok = tokS[r];
                if (tok >= 0) {
                    float gt = gateS[r];
                    float* orow = out + (size_t)tok * DM;
                    #pragma unroll
                    for (int ni = 0; ni < 8; ni++) {
                        int col = wn * 64 + ni * 8 + tg * 2;
                        float2 v;
                        v.x = (acc[mi][ni][rr * 2 + 0] + biasS[col])     * gt;
                        v.y = (acc[mi][ni][rr * 2 + 1] + biasS[col + 1]) * gt;
                        *(float2*)(orow + col) = v;
                    }
                }
            }
        }
    }
}

// ---------------- kernel 5: re-zero counters for next graph replay ----------
__global__ void ztail_kernel() {
    if (threadIdx.x < NE) g_cnt[threadIdx.x] = 0;
}

// ---------------- launch -----------------------------------------------------
extern "C" void kernel_launch(void* const* d_in, const int* in_sizes, int n_in,
                              void* d_out, int out_size)
{
    const float* x  = (const float*)d_in[0];
    const float* wg = (const float*)d_in[1];
    const float* W1 = (const float*)d_in[2];
    const float* b1 = (const float*)d_in[3];
    const float* W2 = (const float*)d_in[4];
    const float* b2 = (const float*)d_in[5];
    float* out = (float*)d_out;

    const int rt_smem = (128 * 264 + NE * DM) * 4;
    const int ff_smem = 64 * WS_S * 4 + MT * XS_H * 2 + DM * 4 + MT * 4 + MT * 4;
    cudaFuncSetAttribute(routing_kernel,
                         cudaFuncAttributeMaxDynamicSharedMemorySize, rt_smem);
    cudaFuncSetAttribute(ffn1_kernel,
                         cudaFuncAttributeMaxDynamicSharedMemorySize, ff_smem);
    cudaFuncSetAttribute(ffn2_kernel,
                         cudaFuncAttributeMaxDynamicSharedMemorySize, ff_smem);

    routing_kernel<<<NTOK / 128, 256, rt_smem>>>(x, wg);      // 1
    perm_kernel<<<64, 1024>>>();                              // 2
    ffn1_kernel<<<NE * CPE, FT, ff_smem>>>(x, W1, b1);        // 3
    ffn2_kernel<<<NE * CPE, FT, ff_smem>>>(W2, b2, out);      // 4 (profiled)
    ztail_kernel<<<1, 32>>>();                                // 5
}